// round 6
// baseline (speedup 1.0000x reference)
#include <cuda_runtime.h>
#include <cuda_bf16.h>
#include <cuda_fp8.h>
#include <math.h>
#include <stdint.h>

#define DIM       128
#define NSPECIAL  4
#define MAX_POS   8192
#define MAX_LT    80
#define NSPLIT    2
#define NSTAGE    3

// smem byte layout
#define LSTRIDE8   144                 // fp8 tile row stride (bytes)
#define PSTRIDE8   80                  // P buffer row stride (bytes)
#define OFF_LANG   0                   // 128*144 = 18432
#define OFF_STG    18432               // 3 stages of (L 18432 + LT 18432)
#define STAGE_B    36864
#define OFF_P      (OFF_STG + NSTAGE * STAGE_B)       // 129024
#define SMEM_TOT   (OFF_P + 8 * 32 * PSTRIDE8)        // 149504

// ---- static device scratch ----
__device__ __align__(16) float    g_lang [MAX_POS * DIM];
__device__ __align__(16) uint8_t  g_lang8[MAX_POS * DIM];
__device__ __align__(16) uint8_t  g_L8   [MAX_LT * 128 * DIM];   // [tile][lat][dim], x64
__device__ __align__(16) uint8_t  g_LT8  [MAX_LT * 128 * DIM];   // [tile][dim][lat], x64
__device__ __align__(16) float    g_O    [NSPLIT][MAX_POS * DIM];
__device__ float                  g_z    [NSPLIT][2][MAX_POS];

// ---------------------------------------------------------------------------
// PTX helpers
// ---------------------------------------------------------------------------
__device__ __forceinline__ void mma_fp8(float* d, const uint32_t* a, const uint32_t* b) {
    asm volatile(
        "mma.sync.aligned.m16n8k32.row.col.f32.e4m3.e4m3.f32 "
        "{%0,%1,%2,%3},{%4,%5,%6,%7},{%8,%9},{%0,%1,%2,%3};\n"
        : "+f"(d[0]), "+f"(d[1]), "+f"(d[2]), "+f"(d[3])
        : "r"(a[0]), "r"(a[1]), "r"(a[2]), "r"(a[3]), "r"(b[0]), "r"(b[1]));
}
__device__ __forceinline__ void cpa16(uint32_t smem_dst, const void* gsrc) {
    asm volatile("cp.async.cg.shared.global [%0], [%1], 16;\n" :: "r"(smem_dst), "l"(gsrc));
}
#define CPA_COMMIT()  asm volatile("cp.async.commit_group;\n" ::: "memory")
#define CPA_WAIT0()   asm volatile("cp.async.wait_group 0;\n" ::: "memory")
#define CPA_WAIT1()   asm volatile("cp.async.wait_group 1;\n" ::: "memory")

// pack (lo, hi) floats -> e4m3x2 u16 (first cvt operand lands in HIGH byte)
__device__ __forceinline__ uint16_t pack_e4m3(float lo, float hi) {
    uint16_t u;
    asm("cvt.rn.satfinite.e4m3x2.f32 %0, %1, %2;" : "=h"(u) : "f"(hi), "f"(lo));
    return u;
}
__device__ __forceinline__ uint8_t f2e4m3(float v) {
    uint16_t u;
    asm("cvt.rn.satfinite.e4m3x2.f32 %0, %1, %2;" : "=h"(u) : "f"(0.f), "f"(v));
    return (uint8_t)(u & 0xff);
}
// exp(S_tilde/64) = ex2(S_tilde * log2(e)/64)
__device__ __forceinline__ float exp64(float x) {
    float r;
    asm("{\n\t.reg .f32 t;\n\tmul.f32 t, %1, 0f3CB8AA3B;\n\t"
        "ex2.approx.f32 %0, t;\n\t}" : "=f"(r) : "f"(x));
    return r;
}

// ---------------------------------------------------------------------------
// Kernel 1: EmbeddingBag(sum) + tanh -> fp32 + fp8
// ---------------------------------------------------------------------------
__global__ void bag_kernel(const float* __restrict__ ngram_emb,
                           const int*   __restrict__ ngram_ids,
                           const int*   __restrict__ ngram_offsets,
                           const int*   __restrict__ x,
                           int n_pos, int n_ngram_total, int n_words)
{
    int pos = blockIdx.x;
    int d   = threadIdx.x;
    float val = 0.0f;
    if (pos < n_pos) {
        int t = x[pos];
        if (t >= NSPECIAL) {
            int v   = t - NSPECIAL;
            int off = ngram_offsets[v];
            int end = (v + 1 < n_words) ? ngram_offsets[v + 1] : n_ngram_total;
            float a0 = 0.f, a1 = 0.f, a2 = 0.f, a3 = 0.f;
            int j = off;
            for (; j + 3 < end; j += 4) {
                int i0 = ngram_ids[j], i1 = ngram_ids[j+1];
                int i2 = ngram_ids[j+2], i3 = ngram_ids[j+3];
                a0 += ngram_emb[(size_t)i0 * DIM + d];
                a1 += ngram_emb[(size_t)i1 * DIM + d];
                a2 += ngram_emb[(size_t)i2 * DIM + d];
                a3 += ngram_emb[(size_t)i3 * DIM + d];
            }
            for (; j < end; ++j)
                a0 += ngram_emb[(size_t)ngram_ids[j] * DIM + d];
            val = tanhf((a0 + a1) + (a2 + a3));
        }
    }
    g_lang [pos * DIM + d] = val;
    g_lang8[pos * DIM + d] = f2e4m3(val);
}

// ---------------------------------------------------------------------------
// Kernel 2: latent -> fp8 (x64), direct + transposed, zero-padded tiles
// ---------------------------------------------------------------------------
__global__ void conv_latent8(const float* __restrict__ latent, int n_latent, int total)
{
    int idx = blockIdx.x * 256 + threadIdx.x;
    if (idx >= total) return;
    int t = idx >> 14, rem = idx & 16383;
    int r = rem >> 7, c = rem & 127;
    // L8: [t][lat=r][dim=c]
    int gl = t * 128 + r;
    g_L8[idx] = f2e4m3(gl < n_latent ? latent[(size_t)gl * DIM + c] * 64.f : 0.f);
    // LT8: [t][dim=r][lat=c]
    int gl2 = t * 128 + c;
    g_LT8[idx] = f2e4m3(gl2 < n_latent ? latent[(size_t)gl2 * DIM + r] * 64.f : 0.f);
}

// ---------------------------------------------------------------------------
// Kernel 3: fp8 register/smem flash attention.
// CTA = 128 tokens, 256 thr = 8 warps (wm 0..3 token blocks, wn 0..1 lat halves)
// ---------------------------------------------------------------------------
__global__ __launch_bounds__(256, 1)
void attn_fp8(int n_pos, int n_latent)
{
    extern __shared__ char sm8[];

    const int tid  = threadIdx.x;
    const int lane = tid & 31;
    const int warp = tid >> 5;
    const int wm   = warp & 3;
    const int wn   = warp >> 2;
    const int g    = lane >> 2;     // row group 0..7
    const int q    = lane & 3;      // quad col
    const int pos0 = blockIdx.x * 128;
    const int split = blockIdx.y;

    const int TT   = (n_latent + 127) >> 7;
    const int half = (TT + 1) >> 1;
    const int t0   = split ? half : 0;
    const int cnt  = split ? (TT - half) : half;

    char* lang_s = sm8 + OFF_LANG;
    char* P_s    = sm8 + OFF_P + warp * (32 * PSTRIDE8);
    const uint32_t stg_u0 = (uint32_t)__cvta_generic_to_shared(sm8) + OFF_STG;

    // ---- load lang fp8 tile (128 x 128 B) ----
    for (int ch = tid; ch < 1024; ch += 256) {
        int r = ch >> 3, c = (ch & 7) << 4;
        *(uint4*)(lang_s + r * LSTRIDE8 + c) =
            *(const uint4*)(g_lang8 + (size_t)(pos0 + r) * DIM + c);
    }

    // ---- prologue: cp.async stages 0,1 ----
#pragma unroll 1
    for (int pf = 0; pf < 2; ++pf) {
        if (pf < cnt) {
            const uint8_t* L  = g_L8  + (size_t)(t0 + pf) * 128 * DIM;
            const uint8_t* LT = g_LT8 + (size_t)(t0 + pf) * 128 * DIM;
            uint32_t dst = stg_u0 + pf * STAGE_B;
            for (int ch = tid; ch < 1024; ch += 256) {
                int r = ch >> 3, c = (ch & 7) << 4;
                cpa16(dst + r * LSTRIDE8 + c,         L  + r * DIM + c);
                cpa16(dst + 18432 + r * LSTRIDE8 + c, LT + r * DIM + c);
            }
            CPA_COMMIT();
        }
    }

    float o[2][16][4];
    float zacc[2][2];
#pragma unroll
    for (int mi = 0; mi < 2; ++mi) {
        zacc[mi][0] = 0.f; zacc[mi][1] = 0.f;
#pragma unroll
        for (int nj = 0; nj < 16; ++nj)
#pragma unroll
            for (int p = 0; p < 4; ++p) o[mi][nj][p] = 0.f;
    }

    for (int t = 0; t < cnt; ++t) {
        if (t + 1 < cnt) CPA_WAIT1(); else CPA_WAIT0();
        __syncthreads();
        if (t + 2 < cnt) {
            const uint8_t* L  = g_L8  + (size_t)(t0 + t + 2) * 128 * DIM;
            const uint8_t* LT = g_LT8 + (size_t)(t0 + t + 2) * 128 * DIM;
            uint32_t dst = stg_u0 + ((t + 2) % NSTAGE) * STAGE_B;
            for (int ch = tid; ch < 1024; ch += 256) {
                int r = ch >> 3, c = (ch & 7) << 4;
                cpa16(dst + r * LSTRIDE8 + c,         L  + r * DIM + c);
                cpa16(dst + 18432 + r * LSTRIDE8 + c, LT + r * DIM + c);
            }
            CPA_COMMIT();
        }
        char* Lst  = sm8 + OFF_STG + (t % NSTAGE) * STAGE_B;
        char* LTst = Lst + 18432;

        // ---- GEMM1: s[32 tok x 64 lat(own)] = lang @ L^T  (k = 128 dims) ----
        float s[2][8][4];
#pragma unroll
        for (int mi = 0; mi < 2; ++mi)
#pragma unroll
            for (int j = 0; j < 8; ++j)
#pragma unroll
                for (int p = 0; p < 4; ++p) s[mi][j][p] = 0.f;

#pragma unroll
        for (int kb = 0; kb < 4; ++kb) {
            const int kc = kb * 32 + q * 4;
            uint32_t a[2][4];
#pragma unroll
            for (int mi = 0; mi < 2; ++mi) {
                const char* ab = lang_s + (wm * 32 + mi * 16 + g) * LSTRIDE8 + kc;
                a[mi][0] = *(const uint32_t*)(ab);
                a[mi][1] = *(const uint32_t*)(ab + 8 * LSTRIDE8);
                a[mi][2] = *(const uint32_t*)(ab + 16);
                a[mi][3] = *(const uint32_t*)(ab + 8 * LSTRIDE8 + 16);
            }
#pragma unroll
            for (int j = 0; j < 8; ++j) {
                const char* bb = Lst + (wn * 64 + j * 8 + g) * LSTRIDE8 + kc;
                uint32_t b[2];
                b[0] = *(const uint32_t*)(bb);
                b[1] = *(const uint32_t*)(bb + 16);
#pragma unroll
                for (int mi = 0; mi < 2; ++mi)
                    mma_fp8(s[mi][j], a[mi], b);
            }
        }

        // ---- exp (descale folded) + tail mask + z + P -> warp-private smem ----
        const int lbase = (t0 + t) * 128 + wn * 64;
        if (lbase + 64 <= n_latent) {
#pragma unroll
            for (int mi = 0; mi < 2; ++mi)
#pragma unroll
                for (int j = 0; j < 8; ++j) {
                    float e0 = exp64(s[mi][j][0]);
                    float e1 = exp64(s[mi][j][1]);
                    float e2 = exp64(s[mi][j][2]);
                    float e3 = exp64(s[mi][j][3]);
                    zacc[mi][0] += e0 + e1;
                    zacc[mi][1] += e2 + e3;
                    *(uint16_t*)(P_s + (mi * 16 + g)     * PSTRIDE8 + j * 8 + q * 2) = pack_e4m3(e0, e1);
                    *(uint16_t*)(P_s + (mi * 16 + g + 8) * PSTRIDE8 + j * 8 + q * 2) = pack_e4m3(e2, e3);
                }
        } else {
            const int c2 = q << 1;
#pragma unroll
            for (int mi = 0; mi < 2; ++mi)
#pragma unroll
                for (int j = 0; j < 8; ++j) {
                    int g0 = lbase + 8 * j + c2;
                    float e0 = (g0     < n_latent) ? exp64(s[mi][j][0]) : 0.f;
                    float e1 = (g0 + 1 < n_latent) ? exp64(s[mi][j][1]) : 0.f;
                    float e2 = (g0     < n_latent) ? exp64(s[mi][j][2]) : 0.f;
                    float e3 = (g0 + 1 < n_latent) ? exp64(s[mi][j][3]) : 0.f;
                    zacc[mi][0] += e0 + e1;
                    zacc[mi][1] += e2 + e3;
                    *(uint16_t*)(P_s + (mi * 16 + g)     * PSTRIDE8 + j * 8 + q * 2) = pack_e4m3(e0, e1);
                    *(uint16_t*)(P_s + (mi * 16 + g + 8) * PSTRIDE8 + j * 8 + q * 2) = pack_e4m3(e2, e3);
                }
        }
        __syncwarp();

        // ---- GEMM2: o[32 tok x 128 dim] += P @ L  (k = own 64 lats) ----
#pragma unroll
        for (int kb = 0; kb < 2; ++kb) {
            const int kc = kb * 32 + q * 4;
            uint32_t a[2][4];
#pragma unroll
            for (int mi = 0; mi < 2; ++mi) {
                const char* ab = P_s + (mi * 16 + g) * PSTRIDE8 + kc;
                a[mi][0] = *(const uint32_t*)(ab);
                a[mi][1] = *(const uint32_t*)(ab + 8 * PSTRIDE8);
                a[mi][2] = *(const uint32_t*)(ab + 16);
                a[mi][3] = *(const uint32_t*)(ab + 8 * PSTRIDE8 + 16);
            }
#pragma unroll
            for (int nj = 0; nj < 16; ++nj) {
                const char* bb = LTst + (nj * 8 + g) * LSTRIDE8 + wn * 64 + kc;
                uint32_t b[2];
                b[0] = *(const uint32_t*)(bb);
                b[1] = *(const uint32_t*)(bb + 16);
#pragma unroll
                for (int mi = 0; mi < 2; ++mi)
                    mma_fp8(o[mi][nj], a[mi], b);
            }
        }
    }

    // ---- z partials ----
#pragma unroll
    for (int mi = 0; mi < 2; ++mi)
#pragma unroll
        for (int h = 0; h < 2; ++h) {
            float zz = zacc[mi][h];
            zz += __shfl_xor_sync(0xffffffffu, zz, 1);
            zz += __shfl_xor_sync(0xffffffffu, zz, 2);
            if (q == 0) {
                int r = pos0 + wm * 32 + mi * 16 + g + h * 8;
                g_z[split][wn][r] = zz;
            }
        }

    // ---- O combine across wn pair via smem overlay on the stage region ----
    float* ored = (float*)(sm8 + OFF_STG);          // 64 KB
    __syncthreads();
    const int r0 = wm * 32 + g;
    const int c0 = q << 1;
    if (wn == 0) {
#pragma unroll
        for (int mi = 0; mi < 2; ++mi)
#pragma unroll
            for (int nj = 0; nj < 16; ++nj) {
                *(float2*)&ored[(r0 + mi * 16)     * 128 + nj * 8 + c0] = make_float2(o[mi][nj][0], o[mi][nj][1]);
                *(float2*)&ored[(r0 + mi * 16 + 8) * 128 + nj * 8 + c0] = make_float2(o[mi][nj][2], o[mi][nj][3]);
            }
    }
    __syncthreads();
    if (wn == 1) {
        float* dst = g_O[split] + (size_t)pos0 * DIM;
#pragma unroll
        for (int mi = 0; mi < 2; ++mi)
#pragma unroll
            for (int nj = 0; nj < 16; ++nj) {
                int ra = (r0 + mi * 16) * 128 + nj * 8 + c0;
                int rb = ra + 8 * 128;
                float2 pa = *(float2*)&ored[ra];
                float2 pb = *(float2*)&ored[rb];
                *(float2*)&dst[ra] = make_float2(pa.x + o[mi][nj][0], pa.y + o[mi][nj][1]);
                *(float2*)&dst[rb] = make_float2(pb.x + o[mi][nj][2], pb.y + o[mi][nj][3]);
            }
    }
}

// ---------------------------------------------------------------------------
// Kernel 4: combine splits + lang add + special override (O was x64-scaled
// twice: L scale in GEMM2 only -> O = 64 * sum(exp*L); z unscaled -> /64)
// ---------------------------------------------------------------------------
__global__ void combine_kernel(const float* __restrict__ special,
                               const int*   __restrict__ x,
                               float*       __restrict__ out,
                               int n_pos)
{
    int pos = blockIdx.x;
    int d   = threadIdx.x;
    if (pos >= n_pos) return;
    int t = x[pos];
    float v;
    if (t < NSPECIAL) {
        v = special[t * DIM + d];
    } else {
        float z = g_z[0][0][pos] + g_z[0][1][pos] + g_z[1][0][pos] + g_z[1][1][pos];
        float O = g_O[0][pos * DIM + d] + g_O[1][pos * DIM + d];
        v = g_lang[pos * DIM + d] + O / (64.0f * z);
    }
    out[pos * DIM + d] = v;
}

// ---------------------------------------------------------------------------
extern "C" void kernel_launch(void* const* d_in, const int* in_sizes, int n_in,
                              void* d_out, int out_size)
{
    const float* ngram_emb     = (const float*)d_in[0];
    const float* latent        = (const float*)d_in[1];
    const float* special       = (const float*)d_in[2];
    const int*   ngram_ids     = (const int*)  d_in[3];
    const int*   ngram_offsets = (const int*)  d_in[4];
    const int*   x             = (const int*)  d_in[5];

    int n_pos    = in_sizes[5];
    int n_words  = in_sizes[4];
    int n_ngtot  = in_sizes[3];
    int n_latent = in_sizes[1] / DIM;
    if (n_pos > MAX_POS) n_pos = MAX_POS;
    if (n_latent > MAX_LT * 128) n_latent = MAX_LT * 128;

    float* out = (float*)d_out;

    int gm = (n_pos + 127) / 128;
    int TT = (n_latent + 127) / 128;
    int total = TT * 128 * DIM;

    bag_kernel<<<gm * 128, DIM>>>(ngram_emb, ngram_ids, ngram_offsets, x,
                                  n_pos, n_ngtot, n_words);

    conv_latent8<<<(total + 255) / 256, 256>>>(latent, n_latent, total);

    cudaFuncSetAttribute(attn_fp8,
                         cudaFuncAttributeMaxDynamicSharedMemorySize, SMEM_TOT);
    attn_fp8<<<dim3(gm, NSPLIT), 256, SMEM_TOT>>>(n_pos, n_latent);

    combine_kernel<<<n_pos, DIM>>>(special, x, out, n_pos);
}